// round 16
// baseline (speedup 1.0000x reference)
#include <cuda_runtime.h>
#include <cuda_fp16.h>
#include <cstdint>

// ---------------------------------------------------------------------------
// Problem constants
// ---------------------------------------------------------------------------
#define TT   4096
#define HIDD 4096
#define HH   32
#define DD   64
#define PP   2048
#define NCMB 6400        // combined QKV+small output columns: 3*2048 + 256
#define NGE  4096        // combined gl|g2 expansion columns
#define KGE  128         // ge expansion K

// ---------------------------------------------------------------------------
// Device scratch
// ---------------------------------------------------------------------------
__device__ float d_xc[TT * NCMB];        // combined qkv|small projection out
__device__ float d_ge[TT * NGE];         // combined gl|g2 expansion out (gl pre-decayed)
__device__ float d_q [TT * PP];
__device__ float d_k [TT * PP];
__device__ float d_v [TT * PP];
__device__ float d_bl[TT * HH];

__device__ __half d_xs  [(size_t)TT * HIDD];    // A: x fp16
__device__ __half d_wcs [(size_t)NCMB * HIDD];  // B: combined W^T fp16
__device__ __half d_wos [(size_t)HIDD * PP];    // B: Wo^T fp16
__device__ __half d_os  [(size_t)TT * PP];      // A: gated o fp16
__device__ __half d_ags [(size_t)TT * KGE];     // A: [fa|ga] fp16
__device__ __half d_wges[(size_t)NGE * KGE];    // B: blockdiag exp W^T fp16

// ---------------------------------------------------------------------------
// cp.async / ldmatrix / mma helpers
// ---------------------------------------------------------------------------
__device__ __forceinline__ uint32_t smem_u32(const void* p) {
    uint32_t a;
    asm("{ .reg .u64 t; cvta.to.shared.u64 t, %1; cvt.u32.u64 %0, t; }"
        : "=r"(a) : "l"(p));
    return a;
}
#define CP_ASYNC16(smem, gptr) \
    asm volatile("cp.async.cg.shared.global [%0], [%1], 16;\n" \
                 :: "r"(smem), "l"(gptr))
#define CP_COMMIT() asm volatile("cp.async.commit_group;\n" ::: "memory")
#define CP_WAIT1()  asm volatile("cp.async.wait_group 1;\n" ::: "memory")
#define CP_WAIT0()  asm volatile("cp.async.wait_group 0;\n" ::: "memory")

#define LDMX4(r0, r1, r2, r3, addr)                                       \
    asm volatile("ldmatrix.sync.aligned.m8n8.x4.shared.b16 "              \
                 "{%0, %1, %2, %3}, [%4];"                                \
                 : "=r"(r0), "=r"(r1), "=r"(r2), "=r"(r3) : "r"(addr))

#define MMA16816(c0, c1, c2, c3, a0, a1, a2, a3, b0, b1)                  \
    asm volatile("mma.sync.aligned.m16n8k16.row.col.f32.f16.f16.f32 "     \
                 "{%0, %1, %2, %3}, {%4, %5, %6, %7}, {%8, %9}, "         \
                 "{%0, %1, %2, %3};"                                      \
                 : "+f"(c0), "+f"(c1), "+f"(c2), "+f"(c3)                 \
                 : "r"(a0), "r"(a1), "r"(a2), "r"(a3), "r"(b0), "r"(b1))

// ---------------------------------------------------------------------------
// fp16 HMMA GEMM:  C = A @ B^T  (fp32 accum/out)
// A: [M,K] fp16 row-major.  B: [N,K] fp16 row-major.
// Block 128x128, BK=64, 8 warps (2x4), warp tile 64x32.
// 3-stage cp.async pipeline, ONE __syncthreads per 64-wide K-chunk.
// DECAY=true (separate instantiation; used only for the expansion GEMM)
// applies v <- exp(-exp(Alog[c>>6]) * softplus(v + dtb[c])) for cols < 2048.
// ---------------------------------------------------------------------------
#define BKH     72                      // 64 halves + 8 pad (144 B rows)
#define STG_H   (2 * 128 * BKH)         // halves per stage (A then B)
#define NSTAGE  3

__device__ __forceinline__ float decay_xform(float v, float d, float al) {
    float xv = v + d;
    float sp = (xv > 20.f) ? xv : __logf(1.f + __expf(xv));
    return __expf(-al * sp);
}

template <bool DECAY>
__global__ void __launch_bounds__(256, 2)
mma_gemm_kernel(const __half* __restrict__ A,
                const __half* __restrict__ B,
                float* __restrict__ C, int K, int ldc,
                const float* __restrict__ dtb,
                const float* __restrict__ Alog)
{
    extern __shared__ __align__(16) __half smem[];
    const uint32_t sbase = smem_u32(smem);

    const int tid   = threadIdx.x;
    const int wid   = tid >> 5;
    const int lane  = tid & 31;
    const int warpM = wid >> 2;          // 0..1
    const int warpN = wid & 3;           // 0..3
    const int rowBase = blockIdx.y * 128;
    const int colBase = blockIdx.x * 128;

    const int nIter = K >> 6;            // K/64 chunks

    float acc[4][4][4];
#pragma unroll
    for (int i = 0; i < 4; i++)
#pragma unroll
        for (int j = 0; j < 4; j++)
#pragma unroll
            for (int r = 0; r < 4; r++) acc[i][j][r] = 0.f;

    const int ldr  = tid >> 3;           // 0..31
    const int ldc8 = (tid & 7) * 8;      // 0..56 step 8

#define LOAD_STAGE(j, s)                                                        \
    do {                                                                        \
        int _kOff = (j) << 6;                                                   \
        uint32_t _sA = sbase + (uint32_t)(s) * (STG_H * 2);                     \
        uint32_t _sB = _sA + 128 * BKH * 2;                                     \
        _Pragma("unroll")                                                       \
        for (int _i = 0; _i < 4; _i++) {                                        \
            int _r = ldr + _i * 32;                                             \
            CP_ASYNC16(_sA + (_r * BKH + ldc8) * 2,                             \
                       A + (size_t)(rowBase + _r) * K + _kOff + ldc8);          \
        }                                                                       \
        _Pragma("unroll")                                                       \
        for (int _i = 0; _i < 4; _i++) {                                        \
            int _r = ldr + _i * 32;                                             \
            CP_ASYNC16(_sB + (_r * BKH + ldc8) * 2,                             \
                       B + (size_t)(colBase + _r) * K + _kOff + ldc8);          \
        }                                                                       \
        CP_COMMIT();                                                            \
    } while (0)

    LOAD_STAGE(0, 0);
    if (nIter > 1) LOAD_STAGE(1, 1); else CP_COMMIT();

    const int aRow = (lane & 15);
    const int aKof = (lane >> 4) * 8;
    const int bNof = ((lane >> 4) & 1) * 8 + (lane & 7);
    const int bKof = ((lane >> 3) & 1) * 8;

    int s = 0;
    for (int it = 0; it < nIter; it++) {
        CP_WAIT1();
        __syncthreads();
        // stage (s+2)%3 was computed in iteration it-1; barrier above protects it.
        int jn = it + 2;
        if (jn < nIter) {
            int sn = s + 2; if (sn >= NSTAGE) sn -= NSTAGE;
            LOAD_STAGE(jn, sn);
        } else {
            CP_COMMIT();     // keep group accounting aligned with CP_WAIT1
        }

        uint32_t aBase = sbase + (uint32_t)s * (STG_H * 2) +
                         (warpM * 64) * (BKH * 2);
        uint32_t bBase = sbase + (uint32_t)s * (STG_H * 2) + 128 * BKH * 2 +
                         (warpN * 32) * (BKH * 2);

#pragma unroll
        for (int kk = 0; kk < 4; kk++) {
            uint32_t a[4][4];
            uint32_t b[2][4];
#pragma unroll
            for (int mi = 0; mi < 4; mi++) {
                uint32_t ad = aBase + ((mi * 16 + aRow) * BKH + kk * 16 + aKof) * 2;
                LDMX4(a[mi][0], a[mi][1], a[mi][2], a[mi][3], ad);
            }
#pragma unroll
            for (int nb = 0; nb < 2; nb++) {
                uint32_t bd = bBase + ((nb * 16 + bNof) * BKH + kk * 16 + bKof) * 2;
                LDMX4(b[nb][0], b[nb][1], b[nb][2], b[nb][3], bd);
            }
#pragma unroll
            for (int mi = 0; mi < 4; mi++) {
#pragma unroll
                for (int ni = 0; ni < 4; ni++) {
                    int nb = ni >> 1;
                    int hi = (ni & 1) * 2;
                    MMA16816(acc[mi][ni][0], acc[mi][ni][1],
                             acc[mi][ni][2], acc[mi][ni][3],
                             a[mi][0], a[mi][1], a[mi][2], a[mi][3],
                             b[nb][hi], b[nb][hi + 1]);
                }
            }
        }
        if (++s == NSTAGE) s = 0;
    }
    CP_WAIT0();

    const int erow = rowBase + warpM * 64 + (lane >> 2);
    const int ecol = colBase + warpN * 32 + (lane & 3) * 2;
#pragma unroll
    for (int mi = 0; mi < 4; mi++) {
#pragma unroll
        for (int ni = 0; ni < 4; ni++) {
            int c0 = ecol + ni * 8;
            float v0 = acc[mi][ni][0], v1 = acc[mi][ni][1];
            float v2 = acc[mi][ni][2], v3 = acc[mi][ni][3];
            if (DECAY) {
                if (colBase < 2048) {        // uniform per CTA (128-aligned tiles)
                    float dt0 = dtb[c0], dt1 = dtb[c0 + 1];
                    float al  = __expf(Alog[c0 >> 6]);
                    v0 = decay_xform(v0, dt0, al);
                    v1 = decay_xform(v1, dt1, al);
                    v2 = decay_xform(v2, dt0, al);
                    v3 = decay_xform(v3, dt1, al);
                }
            }
            float* p0 = C + (size_t)(erow + mi * 16) * ldc + c0;
            float* p1 = p0 + 8 * (size_t)ldc;
            *reinterpret_cast<float2*>(p0) = make_float2(v0, v1);
            *reinterpret_cast<float2*>(p1) = make_float2(v2, v3);
        }
    }
}

// ---------------------------------------------------------------------------
// Prep kernels — plain fp16 conversion
// ---------------------------------------------------------------------------
__global__ void convert_fp16_kernel(const float* __restrict__ x,
                                    __half* __restrict__ out, size_t n)
{
    for (size_t i = (size_t)blockIdx.x * blockDim.x + threadIdx.x; i < n;
         i += (size_t)gridDim.x * blockDim.x) {
        out[i] = __float2half(x[i]);
    }
}

// in [R, C] fp32 -> out [C, R] fp16
__global__ void transpose_h_kernel(const float* __restrict__ in,
                                   __half* __restrict__ out,
                                   int R, int C)
{
    __shared__ float t[32][33];
    int c0 = blockIdx.x * 32, r0 = blockIdx.y * 32;
    int x = threadIdx.x, y = threadIdx.y;
#pragma unroll
    for (int i = 0; i < 32; i += 8)
        t[y + i][x] = in[(size_t)(r0 + y + i) * C + c0 + x];
    __syncthreads();
#pragma unroll
    for (int i = 0; i < 32; i += 8) {
        float v = t[x][y + i];
        out[(size_t)(c0 + y + i) * R + r0 + x] = __float2half(v);
    }
}

// pack Wfa[HID,64] | Wga[HID,64] | Wb[HID,32] -> W' [256, HID] fp16
__global__ void pack_small_kernel(const float* __restrict__ Wfa,
                                  const float* __restrict__ Wga,
                                  const float* __restrict__ Wb,
                                  __half* __restrict__ out)
{
    size_t total = (size_t)256 * HIDD;
    for (size_t i = (size_t)blockIdx.x * blockDim.x + threadIdx.x; i < total;
         i += (size_t)gridDim.x * blockDim.x) {
        int n = (int)(i / HIDD);
        int k = (int)(i % HIDD);
        float v = 0.f;
        if (n < 64)       v = Wfa[(size_t)k * 64 + n];
        else if (n < 128) v = Wga[(size_t)k * 64 + (n - 64)];
        else if (n < 160) v = Wb[(size_t)k * 32 + (n - 128)];
        out[i] = __float2half(v);
    }
}

// block-diagonal expansion weights: W' [NGE, 128] fp16
// rows 0..2047: Wfb^T in cols 0..63 ; rows 2048..4095: Wgb^T in cols 64..127
__global__ void pack_ge_kernel(const float* __restrict__ Wfb,
                               const float* __restrict__ Wgb,
                               __half* __restrict__ out)
{
    size_t total = (size_t)NGE * KGE;
    for (size_t i = (size_t)blockIdx.x * blockDim.x + threadIdx.x; i < total;
         i += (size_t)gridDim.x * blockDim.x) {
        int n = (int)(i >> 7);
        int k = (int)(i & 127);
        float v = 0.f;
        if (n < 2048) {
            if (k < 64) v = Wfb[(size_t)k * PP + n];
        } else {
            if (k >= 64) v = Wgb[(size_t)(k - 64) * PP + (n - 2048)];
        }
        out[i] = __float2half(v);
    }
}

// extract fa|ga (fp16 [T,128]) + beta from combined GEMM out
__global__ void extract_small_kernel(const float* __restrict__ xc,
                                     __half* __restrict__ ags,
                                     float* __restrict__ bl)
{
    size_t total = (size_t)TT * 160;
    for (size_t i = (size_t)blockIdx.x * blockDim.x + threadIdx.x; i < total;
         i += (size_t)gridDim.x * blockDim.x) {
        int m = (int)(i / 160);
        int c = (int)(i % 160);
        float v = xc[(size_t)m * NCMB + 6144 + c];
        if (c < 128) {
            ags[(size_t)m * KGE + c] = __float2half(v);
        } else {
            bl[(size_t)m * 32 + (c - 128)] = v;
        }
    }
}

// ---------------------------------------------------------------------------
// conv+silu (+l2norm) — x has row stride ldx (combined buffer)
// ---------------------------------------------------------------------------
__global__ void conv_silu_kernel(const float* __restrict__ x, int ldx,
                                 const float* __restrict__ w,
                                 float* __restrict__ y, int mode)
{
    const int t    = blockIdx.x;
    const int h    = blockIdx.y * 8 + (threadIdx.x >> 5);
    const int lane = threadIdx.x & 31;

    float val[2];
    float ss = 0.f;
#pragma unroll
    for (int e = 0; e < 2; e++) {
        int d = lane + e * 32;
        int p = h * DD + d;
        const float* xp = x + p;
        float4 wv = *reinterpret_cast<const float4*>(w + p * 4);
        float acc = xp[(size_t)t * ldx] * wv.w;
        if (t >= 1) acc = fmaf(xp[(size_t)(t - 1) * ldx], wv.z, acc);
        if (t >= 2) acc = fmaf(xp[(size_t)(t - 2) * ldx], wv.y, acc);
        if (t >= 3) acc = fmaf(xp[(size_t)(t - 3) * ldx], wv.x, acc);
        float sv = acc / (1.f + __expf(-acc));
        val[e] = sv;
        ss += sv * sv;
    }
    if (mode > 0) {
        ss += __shfl_xor_sync(0xffffffffu, ss, 16);
        ss += __shfl_xor_sync(0xffffffffu, ss, 8);
        ss += __shfl_xor_sync(0xffffffffu, ss, 4);
        ss += __shfl_xor_sync(0xffffffffu, ss, 2);
        ss += __shfl_xor_sync(0xffffffffu, ss, 1);
        float r = rsqrtf(ss + 1e-6f);
        if (mode == 2) r *= 0.125f;
        val[0] *= r; val[1] *= r;
    }
    size_t base = (size_t)t * PP + h * DD;
    y[base + lane]      = val[0];
    y[base + lane + 32] = val[1];
}

// ---------------------------------------------------------------------------
// KDA scan. Grid (2, HH): each CTA has 4 warps (one per SMSP) and owns
// v-cols [cb*32, cb*32+32) of head h; warp w owns 8 cols. e/k/q rows are
// shared by the 4 warps through L1. beta sigmoid applied at load time
// (2 steps ahead, off the critical path; bitwise-identical value).
// ---------------------------------------------------------------------------
__device__ __forceinline__ float kda_step(float S[16],
                                          const float eg[16], const float kk[16],
                                          const float qq[16], float vv, float bsig)
{
    float vp0 = 0.f, vp1 = 0.f, vp2 = 0.f, vp3 = 0.f;
#pragma unroll
    for (int j = 0; j < 16; j += 4) {
        float s0 = S[j + 0] * eg[j + 0]; S[j + 0] = s0; vp0 = fmaf(kk[j + 0], s0, vp0);
        float s1 = S[j + 1] * eg[j + 1]; S[j + 1] = s1; vp1 = fmaf(kk[j + 1], s1, vp1);
        float s2 = S[j + 2] * eg[j + 2]; S[j + 2] = s2; vp2 = fmaf(kk[j + 2], s2, vp2);
        float s3 = S[j + 3] * eg[j + 3]; S[j + 3] = s3; vp3 = fmaf(kk[j + 3], s3, vp3);
    }
    float vpred = (vp0 + vp1) + (vp2 + vp3);
    vpred += __shfl_xor_sync(0xffffffffu, vpred, 8);
    vpred += __shfl_xor_sync(0xffffffffu, vpred, 16);
    float delta = (vv - vpred) * bsig;
    float o0 = 0.f, o1 = 0.f, o2 = 0.f, o3 = 0.f;
#pragma unroll
    for (int j = 0; j < 16; j += 4) {
        S[j + 0] = fmaf(kk[j + 0], delta, S[j + 0]); o0 = fmaf(qq[j + 0], S[j + 0], o0);
        S[j + 1] = fmaf(kk[j + 1], delta, S[j + 1]); o1 = fmaf(qq[j + 1], S[j + 1], o1);
        S[j + 2] = fmaf(kk[j + 2], delta, S[j + 2]); o2 = fmaf(qq[j + 2], S[j + 2], o2);
        S[j + 3] = fmaf(kk[j + 3], delta, S[j + 3]); o3 = fmaf(qq[j + 3], S[j + 3], o3);
    }
    float ov = (o0 + o1) + (o2 + o3);
    ov += __shfl_xor_sync(0xffffffffu, ov, 8);
    ov += __shfl_xor_sync(0xffffffffu, ov, 16);
    return ov;
}

// egg has row stride NGE (view into combined buffer); q/k/v stride PP
__global__ void __launch_bounds__(128, 1)
kda_scan_kernel(const float* __restrict__ qg, const float* __restrict__ kg,
                const float* __restrict__ vg, const float* __restrict__ egg,
                const float* __restrict__ bg, float* __restrict__ og)
{
    const int cb      = blockIdx.x;              // col-half 0..1
    const int h       = blockIdx.y;
    const int warp    = threadIdx.x >> 5;        // 0..3 -> one per SMSP
    const int lane    = threadIdx.x & 31;
    const int quarter = lane >> 3;
    const int col     = (cb << 5) + (warp << 3) + (lane & 7);
    const int kb      = quarter << 4;

    const float* ep  = egg + h * DD + kb;
    const float* kp  = kg  + h * DD + kb;
    const float* qp  = qg  + h * DD + kb;
    const float* vpt = vg  + h * DD + col;
    const float* bpt = bg  + h;

    float S[16];
#pragma unroll
    for (int j = 0; j < 16; j++) S[j] = 0.f;

    // L2 prefetch pointers (warp 0, lanes 0..8): e/k/q/v head rows + beta
    const float* pf = nullptr;
    size_t pfstride = 0;
    if (warp == 0 && lane < 9) {
        if (lane < 8) {
            const float* bases[4] = {egg, kg, qg, vg};
            const size_t strides[4] = {NGE, PP, PP, PP};
            pf = bases[lane >> 1] + h * DD + (lane & 1) * 32;
            pfstride = strides[lane >> 1];
        } else {
            pf = bg + h;
            pfstride = HH;
        }
    }

    float ea[16], ka[16], qa[16], va, ba;
    float eb[16], kbf[16], qb[16], vb, bb;

#define LOADSTAGE(E, KA, QA, V, B, t)                                            \
    do {                                                                         \
        size_t offe = (size_t)(t) * NGE;                                         \
        size_t off  = (size_t)(t) * PP;                                          \
        _Pragma("unroll")                                                        \
        for (int j = 0; j < 16; j += 4) {                                        \
            *reinterpret_cast<float4*>(&E[j])  =                                 \
                *reinterpret_cast<const float4*>(ep + offe + j);                 \
            *reinterpret_cast<float4*>(&KA[j]) =                                 \
                *reinterpret_cast<const float4*>(kp + off + j);                  \
            *reinterpret_cast<float4*>(&QA[j]) =                                 \
                *reinterpret_cast<const float4*>(qp + off + j);                  \
        }                                                                        \
        V = vpt[off];                                                            \
        float _br = bpt[(size_t)(t) * HH];                                       \
        B = 1.f / (1.f + __expf(-_br));                                          \
    } while (0)

    LOADSTAGE(ea, ka, qa, va, ba, 0);
    LOADSTAGE(eb, kbf, qb, vb, bb, 1);

    for (int t = 0; t < TT; t += 2) {
        if (pf) {
            int tp = t + 8;
            if (tp + 1 < TT) {
                const float* p0 = pf + (size_t)tp * pfstride;
                const float* p1 = pf + (size_t)(tp + 1) * pfstride;
                asm volatile("prefetch.global.L2 [%0];" :: "l"(p0));
                asm volatile("prefetch.global.L2 [%0];" :: "l"(p1));
            }
        }
        float ov = kda_step(S, ea, ka, qa, va, ba);
        if (quarter == 0) og[(size_t)t * PP + h * DD + col] = ov;
        if (t + 2 < TT) LOADSTAGE(ea, ka, qa, va, ba, t + 2);

        ov = kda_step(S, eb, kbf, qb, vb, bb);
        if (quarter == 0) og[(size_t)(t + 1) * PP + h * DD + col] = ov;
        if (t + 3 < TT) LOADSTAGE(eb, kbf, qb, vb, bb, t + 3);
    }
#undef LOADSTAGE
}

// gated RMSNorm -> fp16 ([T, PP]); g2 strided (ld = NGE)
__global__ void rms_gate_h_kernel(const float* __restrict__ o,
                                  const float* __restrict__ g2, int ldg,
                                  const float* __restrict__ wn,
                                  __half* __restrict__ os)
{
    const int t    = blockIdx.x;
    const int h    = blockIdx.y * 8 + (threadIdx.x >> 5);
    const int lane = threadIdx.x & 31;
    size_t base  = (size_t)t * PP + h * DD;
    size_t gbase = (size_t)t * ldg + h * DD;

    float a = o[base + lane];
    float b = o[base + lane + 32];
    float ss = a * a + b * b;
    ss += __shfl_xor_sync(0xffffffffu, ss, 16);
    ss += __shfl_xor_sync(0xffffffffu, ss, 8);
    ss += __shfl_xor_sync(0xffffffffu, ss, 4);
    ss += __shfl_xor_sync(0xffffffffu, ss, 2);
    ss += __shfl_xor_sync(0xffffffffu, ss, 1);
    float r = rsqrtf(ss * (1.f / 64.f) + 1e-5f);

    float ga = g2[gbase + lane];
    float gb = g2[gbase + lane + 32];
    float va = a * r * wn[lane]      * (1.f / (1.f + __expf(-ga)));
    float vb = b * r * wn[lane + 32] * (1.f / (1.f + __expf(-gb)));

    os[base + lane]      = __float2half(va);
    os[base + lane + 32] = __float2half(vb);
}

// ---------------------------------------------------------------------------
// Host launcher
// NOTE launch ordering: the ncu harness profiles launch index 5 (-s 5 -c 1).
// Order is arranged so launch #5 is the big projection GEMM:
//   0:convert 1:tQ 2:tK 3:tV 4:pack_small 5:projGEMM ...
// tWo and pack_ge are moved after the projection GEMM (their consumers come
// later); this changes nothing functionally.
// ---------------------------------------------------------------------------
extern "C" void kernel_launch(void* const* d_in, const int* in_sizes, int n_in,
                              void* d_out, int out_size)
{
    const float* x    = (const float*)d_in[0];
    const float* Wq   = (const float*)d_in[1];
    const float* Wk   = (const float*)d_in[2];
    const float* Wv   = (const float*)d_in[3];
    const float* Wb   = (const float*)d_in[4];
    const float* Wfa  = (const float*)d_in[5];
    const float* Wfb  = (const float*)d_in[6];
    const float* dtb  = (const float*)d_in[7];
    const float* Alog = (const float*)d_in[8];
    const float* Wga  = (const float*)d_in[9];
    const float* Wgb  = (const float*)d_in[10];
    const float* cq   = (const float*)d_in[11];
    const float* ck   = (const float*)d_in[12];
    const float* cv   = (const float*)d_in[13];
    const float* wno  = (const float*)d_in[14];
    const float* Wo   = (const float*)d_in[15];
    float* out = (float*)d_out;

    static float *pxc = nullptr, *pge, *pq, *pk, *pv, *pbl;
    static __half *pxs, *pwcs, *pwos, *pos, *pags, *pwges;
    if (!pxc) {
        cudaGetSymbolAddress((void**)&pxc, d_xc);
        cudaGetSymbolAddress((void**)&pge, d_ge);
        cudaGetSymbolAddress((void**)&pq,  d_q);
        cudaGetSymbolAddress((void**)&pk,  d_k);
        cudaGetSymbolAddress((void**)&pv,  d_v);
        cudaGetSymbolAddress((void**)&pbl, d_bl);
        cudaGetSymbolAddress((void**)&pxs,  d_xs);
        cudaGetSymbolAddress((void**)&pwcs, d_wcs);
        cudaGetSymbolAddress((void**)&pwos, d_wos);
        cudaGetSymbolAddress((void**)&pos,  d_os);
        cudaGetSymbolAddress((void**)&pags, d_ags);
        cudaGetSymbolAddress((void**)&pwges, d_wges);
        cudaFuncSetAttribute(mma_gemm_kernel<false>,
                             cudaFuncAttributeMaxDynamicSharedMemorySize,
                             NSTAGE * STG_H * 2);
        cudaFuncSetAttribute(mma_gemm_kernel<true>,
                             cudaFuncAttributeMaxDynamicSharedMemorySize,
                             NSTAGE * STG_H * 2);
    }

    dim3 blk(256);
    const size_t smemMMA = NSTAGE * STG_H * 2;   // 110592 B

    // 0-4: prep needed by the projection GEMM
    convert_fp16_kernel<<<2048, 256>>>(x, pxs, (size_t)TT * HIDD);
    transpose_h_kernel<<<dim3(PP / 32, HIDD / 32), dim3(32, 8)>>>(
        Wq, pwcs + (size_t)0 * HIDD, HIDD, PP);
    transpose_h_kernel<<<dim3(PP / 32, HIDD / 32), dim3(32, 8)>>>(
        Wk, pwcs + (size_t)2048 * HIDD, HIDD, PP);
    transpose_h_kernel<<<dim3(PP / 32, HIDD / 32), dim3(32, 8)>>>(
        Wv, pwcs + (size_t)4096 * HIDD, HIDD, PP);
    pack_small_kernel<<<1024, 256>>>(Wfa, Wga, Wb, pwcs + (size_t)6144 * HIDD);

    // 5: ONE combined projection GEMM: [T, 4096] @ [4096, 6400]  (profiled)
    mma_gemm_kernel<false><<<dim3(NCMB / 128, TT / 128), blk, smemMMA>>>(
        pxs, pwcs, pxc, HIDD, NCMB, nullptr, nullptr);

    // 6-8: expansion path
    extract_small_kernel<<<1024, 256>>>(pxc, pags, pbl);
    pack_ge_kernel<<<512, 256>>>(Wfb, Wgb, pwges);
    mma_gemm_kernel<true><<<dim3(NGE / 128, TT / 128), blk, smemMMA>>>(
        pags, pwges, pge, KGE, NGE, dtb, Alog);

    // 9: Wo transpose (only needed by the final GEMM)
    transpose_h_kernel<<<dim3(HIDD / 32, PP / 32), dim3(32, 8)>>>(
        Wo, pwos, PP, HIDD);

    // 10-14: elementwise / scan
    dim3 cgrid(TT, HH / 8);
    conv_silu_kernel<<<cgrid, blk>>>(pxc + 0,    NCMB, cq, pq, 2);
    conv_silu_kernel<<<cgrid, blk>>>(pxc + 2048, NCMB, ck, pk, 1);
    conv_silu_kernel<<<cgrid, blk>>>(pxc + 4096, NCMB, cv, pv, 0);
    kda_scan_kernel<<<dim3(2, HH), 128>>>(pq, pk, pv, pge, pbl, pq /* o in place */);
    rms_gate_h_kernel<<<cgrid, blk>>>(pq, pge + 2048, NGE, wno, pos);

    // 15: output projection on tensor cores
    mma_gemm_kernel<false><<<dim3(HIDD / 128, TT / 128), blk, smemMMA>>>(
        pos, pwos, out, PP, HIDD, nullptr, nullptr);

    (void)in_sizes; (void)n_in; (void)out_size;
}

// round 17
// speedup vs baseline: 1.1937x; 1.1937x over previous
#include <cuda_runtime.h>
#include <cuda_fp16.h>
#include <cstdint>

// ---------------------------------------------------------------------------
// Problem constants
// ---------------------------------------------------------------------------
#define TT   4096
#define HIDD 4096
#define HH   32
#define DD   64
#define PP   2048
#define NCMB 6400        // combined QKV+small output columns: 3*2048 + 256
#define NGE  4096        // combined gl|g2 expansion columns
#define KGE  128         // ge expansion K

// ---------------------------------------------------------------------------
// Device scratch
// ---------------------------------------------------------------------------
__device__ float d_xc[TT * NCMB];        // combined qkv|small projection out
__device__ float d_ge[TT * NGE];         // combined gl|g2 expansion out (gl pre-decayed)
__device__ float d_q [TT * PP];
__device__ float d_k [TT * PP];
__device__ float d_v [TT * PP];
__device__ float d_bl[TT * HH];

__device__ __half d_xs  [(size_t)TT * HIDD];    // A: x fp16
__device__ __half d_wcs [(size_t)NCMB * HIDD];  // B: combined W^T fp16
__device__ __half d_wos [(size_t)HIDD * PP];    // B: Wo^T fp16
__device__ __half d_os  [(size_t)TT * PP];      // A: gated o fp16
__device__ __half d_ags [(size_t)TT * KGE];     // A: [fa|ga] fp16
__device__ __half d_wges[(size_t)NGE * KGE];    // B: blockdiag exp W^T fp16

// ---------------------------------------------------------------------------
// cp.async / ldmatrix / mma helpers
// ---------------------------------------------------------------------------
__device__ __forceinline__ uint32_t smem_u32(const void* p) {
    uint32_t a;
    asm("{ .reg .u64 t; cvta.to.shared.u64 t, %1; cvt.u32.u64 %0, t; }"
        : "=r"(a) : "l"(p));
    return a;
}
#define CP_ASYNC16(smem, gptr) \
    asm volatile("cp.async.cg.shared.global [%0], [%1], 16;\n" \
                 :: "r"(smem), "l"(gptr))
#define CP_COMMIT() asm volatile("cp.async.commit_group;\n" ::: "memory")
#define CP_WAIT1()  asm volatile("cp.async.wait_group 1;\n" ::: "memory")
#define CP_WAIT0()  asm volatile("cp.async.wait_group 0;\n" ::: "memory")

#define LDMX4(r0, r1, r2, r3, addr)                                       \
    asm volatile("ldmatrix.sync.aligned.m8n8.x4.shared.b16 "              \
                 "{%0, %1, %2, %3}, [%4];"                                \
                 : "=r"(r0), "=r"(r1), "=r"(r2), "=r"(r3) : "r"(addr))

#define MMA16816(c0, c1, c2, c3, a0, a1, a2, a3, b0, b1)                  \
    asm volatile("mma.sync.aligned.m16n8k16.row.col.f32.f16.f16.f32 "     \
                 "{%0, %1, %2, %3}, {%4, %5, %6, %7}, {%8, %9}, "         \
                 "{%0, %1, %2, %3};"                                      \
                 : "+f"(c0), "+f"(c1), "+f"(c2), "+f"(c3)                 \
                 : "r"(a0), "r"(a1), "r"(a2), "r"(a3), "r"(b0), "r"(b1))

// ---------------------------------------------------------------------------
// fp16 HMMA GEMM:  C = A @ B^T  (fp32 accum/out)
// A: [M,K] fp16 row-major.  B: [N,K] fp16 row-major.
// Block 128x128, BK=64, 8 warps (2x4), warp tile 64x32.
// 3-stage cp.async pipeline, ONE __syncthreads per 64-wide K-chunk.
// DECAY=true (separate instantiation; used only for the expansion GEMM)
// applies v <- exp(-exp(Alog[c>>6]) * softplus(v + dtb[c])) for cols < 2048.
// ---------------------------------------------------------------------------
#define BKH     72                      // 64 halves + 8 pad (144 B rows)
#define STG_H   (2 * 128 * BKH)         // halves per stage (A then B)
#define NSTAGE  3

__device__ __forceinline__ float decay_xform(float v, float d, float al) {
    float xv = v + d;
    float sp = (xv > 20.f) ? xv : __logf(1.f + __expf(xv));
    return __expf(-al * sp);
}

template <bool DECAY>
__global__ void __launch_bounds__(256, 2)
mma_gemm_kernel(const __half* __restrict__ A,
                const __half* __restrict__ B,
                float* __restrict__ C, int K, int ldc,
                const float* __restrict__ dtb,
                const float* __restrict__ Alog)
{
    extern __shared__ __align__(16) __half smem[];
    const uint32_t sbase = smem_u32(smem);

    const int tid   = threadIdx.x;
    const int wid   = tid >> 5;
    const int lane  = tid & 31;
    const int warpM = wid >> 2;          // 0..1
    const int warpN = wid & 3;           // 0..3
    const int rowBase = blockIdx.y * 128;
    const int colBase = blockIdx.x * 128;

    const int nIter = K >> 6;            // K/64 chunks

    float acc[4][4][4];
#pragma unroll
    for (int i = 0; i < 4; i++)
#pragma unroll
        for (int j = 0; j < 4; j++)
#pragma unroll
            for (int r = 0; r < 4; r++) acc[i][j][r] = 0.f;

    const int ldr  = tid >> 3;           // 0..31
    const int ldc8 = (tid & 7) * 8;      // 0..56 step 8

#define LOAD_STAGE(j, s)                                                        \
    do {                                                                        \
        int _kOff = (j) << 6;                                                   \
        uint32_t _sA = sbase + (uint32_t)(s) * (STG_H * 2);                     \
        uint32_t _sB = _sA + 128 * BKH * 2;                                     \
        _Pragma("unroll")                                                       \
        for (int _i = 0; _i < 4; _i++) {                                        \
            int _r = ldr + _i * 32;                                             \
            CP_ASYNC16(_sA + (_r * BKH + ldc8) * 2,                             \
                       A + (size_t)(rowBase + _r) * K + _kOff + ldc8);          \
        }                                                                       \
        _Pragma("unroll")                                                       \
        for (int _i = 0; _i < 4; _i++) {                                        \
            int _r = ldr + _i * 32;                                             \
            CP_ASYNC16(_sB + (_r * BKH + ldc8) * 2,                             \
                       B + (size_t)(colBase + _r) * K + _kOff + ldc8);          \
        }                                                                       \
        CP_COMMIT();                                                            \
    } while (0)

    LOAD_STAGE(0, 0);
    if (nIter > 1) LOAD_STAGE(1, 1); else CP_COMMIT();

    const int aRow = (lane & 15);
    const int aKof = (lane >> 4) * 8;
    const int bNof = ((lane >> 4) & 1) * 8 + (lane & 7);
    const int bKof = ((lane >> 3) & 1) * 8;

    int s = 0;
    for (int it = 0; it < nIter; it++) {
        CP_WAIT1();
        __syncthreads();
        // stage (s+2)%3 was computed in iteration it-1; barrier above protects it.
        int jn = it + 2;
        if (jn < nIter) {
            int sn = s + 2; if (sn >= NSTAGE) sn -= NSTAGE;
            LOAD_STAGE(jn, sn);
        } else {
            CP_COMMIT();     // keep group accounting aligned with CP_WAIT1
        }

        uint32_t aBase = sbase + (uint32_t)s * (STG_H * 2) +
                         (warpM * 64) * (BKH * 2);
        uint32_t bBase = sbase + (uint32_t)s * (STG_H * 2) + 128 * BKH * 2 +
                         (warpN * 32) * (BKH * 2);

#pragma unroll
        for (int kk = 0; kk < 4; kk++) {
            uint32_t a[4][4];
            uint32_t b[2][4];
#pragma unroll
            for (int mi = 0; mi < 4; mi++) {
                uint32_t ad = aBase + ((mi * 16 + aRow) * BKH + kk * 16 + aKof) * 2;
                LDMX4(a[mi][0], a[mi][1], a[mi][2], a[mi][3], ad);
            }
#pragma unroll
            for (int nb = 0; nb < 2; nb++) {
                uint32_t bd = bBase + ((nb * 16 + bNof) * BKH + kk * 16 + bKof) * 2;
                LDMX4(b[nb][0], b[nb][1], b[nb][2], b[nb][3], bd);
            }
#pragma unroll
            for (int mi = 0; mi < 4; mi++) {
#pragma unroll
                for (int ni = 0; ni < 4; ni++) {
                    int nb = ni >> 1;
                    int hi = (ni & 1) * 2;
                    MMA16816(acc[mi][ni][0], acc[mi][ni][1],
                             acc[mi][ni][2], acc[mi][ni][3],
                             a[mi][0], a[mi][1], a[mi][2], a[mi][3],
                             b[nb][hi], b[nb][hi + 1]);
                }
            }
        }
        if (++s == NSTAGE) s = 0;
    }
    CP_WAIT0();

    const int erow = rowBase + warpM * 64 + (lane >> 2);
    const int ecol = colBase + warpN * 32 + (lane & 3) * 2;
#pragma unroll
    for (int mi = 0; mi < 4; mi++) {
#pragma unroll
        for (int ni = 0; ni < 4; ni++) {
            int c0 = ecol + ni * 8;
            float v0 = acc[mi][ni][0], v1 = acc[mi][ni][1];
            float v2 = acc[mi][ni][2], v3 = acc[mi][ni][3];
            if (DECAY) {
                if (colBase < 2048) {        // uniform per CTA (128-aligned tiles)
                    float dt0 = dtb[c0], dt1 = dtb[c0 + 1];
                    float al  = __expf(Alog[c0 >> 6]);
                    v0 = decay_xform(v0, dt0, al);
                    v1 = decay_xform(v1, dt1, al);
                    v2 = decay_xform(v2, dt0, al);
                    v3 = decay_xform(v3, dt1, al);
                }
            }
            float* p0 = C + (size_t)(erow + mi * 16) * ldc + c0;
            float* p1 = p0 + 8 * (size_t)ldc;
            *reinterpret_cast<float2*>(p0) = make_float2(v0, v1);
            *reinterpret_cast<float2*>(p1) = make_float2(v2, v3);
        }
    }
}

// ---------------------------------------------------------------------------
// Prep kernels — plain fp16 conversion
// ---------------------------------------------------------------------------
__global__ void convert_fp16_kernel(const float* __restrict__ x,
                                    __half* __restrict__ out, size_t n)
{
    for (size_t i = (size_t)blockIdx.x * blockDim.x + threadIdx.x; i < n;
         i += (size_t)gridDim.x * blockDim.x) {
        out[i] = __float2half(x[i]);
    }
}

// in [R, C] fp32 -> out [C, R] fp16
__global__ void transpose_h_kernel(const float* __restrict__ in,
                                   __half* __restrict__ out,
                                   int R, int C)
{
    __shared__ float t[32][33];
    int c0 = blockIdx.x * 32, r0 = blockIdx.y * 32;
    int x = threadIdx.x, y = threadIdx.y;
#pragma unroll
    for (int i = 0; i < 32; i += 8)
        t[y + i][x] = in[(size_t)(r0 + y + i) * C + c0 + x];
    __syncthreads();
#pragma unroll
    for (int i = 0; i < 32; i += 8) {
        float v = t[x][y + i];
        out[(size_t)(c0 + y + i) * R + r0 + x] = __float2half(v);
    }
}

// pack Wfa[HID,64] | Wga[HID,64] | Wb[HID,32] -> W' [256, HID] fp16
__global__ void pack_small_kernel(const float* __restrict__ Wfa,
                                  const float* __restrict__ Wga,
                                  const float* __restrict__ Wb,
                                  __half* __restrict__ out)
{
    size_t total = (size_t)256 * HIDD;
    for (size_t i = (size_t)blockIdx.x * blockDim.x + threadIdx.x; i < total;
         i += (size_t)gridDim.x * blockDim.x) {
        int n = (int)(i / HIDD);
        int k = (int)(i % HIDD);
        float v = 0.f;
        if (n < 64)       v = Wfa[(size_t)k * 64 + n];
        else if (n < 128) v = Wga[(size_t)k * 64 + (n - 64)];
        else if (n < 160) v = Wb[(size_t)k * 32 + (n - 128)];
        out[i] = __float2half(v);
    }
}

// block-diagonal expansion weights: W' [NGE, 128] fp16
// rows 0..2047: Wfb^T in cols 0..63 ; rows 2048..4095: Wgb^T in cols 64..127
__global__ void pack_ge_kernel(const float* __restrict__ Wfb,
                               const float* __restrict__ Wgb,
                               __half* __restrict__ out)
{
    size_t total = (size_t)NGE * KGE;
    for (size_t i = (size_t)blockIdx.x * blockDim.x + threadIdx.x; i < total;
         i += (size_t)gridDim.x * blockDim.x) {
        int n = (int)(i >> 7);
        int k = (int)(i & 127);
        float v = 0.f;
        if (n < 2048) {
            if (k < 64) v = Wfb[(size_t)k * PP + n];
        } else {
            if (k >= 64) v = Wgb[(size_t)(k - 64) * PP + (n - 2048)];
        }
        out[i] = __float2half(v);
    }
}

// extract fa|ga (fp16 [T,128]) + beta from combined GEMM out
__global__ void extract_small_kernel(const float* __restrict__ xc,
                                     __half* __restrict__ ags,
                                     float* __restrict__ bl)
{
    size_t total = (size_t)TT * 160;
    for (size_t i = (size_t)blockIdx.x * blockDim.x + threadIdx.x; i < total;
         i += (size_t)gridDim.x * blockDim.x) {
        int m = (int)(i / 160);
        int c = (int)(i % 160);
        float v = xc[(size_t)m * NCMB + 6144 + c];
        if (c < 128) {
            ags[(size_t)m * KGE + c] = __float2half(v);
        } else {
            bl[(size_t)m * 32 + (c - 128)] = v;
        }
    }
}

// ---------------------------------------------------------------------------
// conv+silu (+l2norm) — x has row stride ldx (combined buffer)
// ---------------------------------------------------------------------------
__global__ void conv_silu_kernel(const float* __restrict__ x, int ldx,
                                 const float* __restrict__ w,
                                 float* __restrict__ y, int mode)
{
    const int t    = blockIdx.x;
    const int h    = blockIdx.y * 8 + (threadIdx.x >> 5);
    const int lane = threadIdx.x & 31;

    float val[2];
    float ss = 0.f;
#pragma unroll
    for (int e = 0; e < 2; e++) {
        int d = lane + e * 32;
        int p = h * DD + d;
        const float* xp = x + p;
        float4 wv = *reinterpret_cast<const float4*>(w + p * 4);
        float acc = xp[(size_t)t * ldx] * wv.w;
        if (t >= 1) acc = fmaf(xp[(size_t)(t - 1) * ldx], wv.z, acc);
        if (t >= 2) acc = fmaf(xp[(size_t)(t - 2) * ldx], wv.y, acc);
        if (t >= 3) acc = fmaf(xp[(size_t)(t - 3) * ldx], wv.x, acc);
        float sv = acc / (1.f + __expf(-acc));
        val[e] = sv;
        ss += sv * sv;
    }
    if (mode > 0) {
        ss += __shfl_xor_sync(0xffffffffu, ss, 16);
        ss += __shfl_xor_sync(0xffffffffu, ss, 8);
        ss += __shfl_xor_sync(0xffffffffu, ss, 4);
        ss += __shfl_xor_sync(0xffffffffu, ss, 2);
        ss += __shfl_xor_sync(0xffffffffu, ss, 1);
        float r = rsqrtf(ss + 1e-6f);
        if (mode == 2) r *= 0.125f;
        val[0] *= r; val[1] *= r;
    }
    size_t base = (size_t)t * PP + h * DD;
    y[base + lane]      = val[0];
    y[base + lane + 32] = val[1];
}

// ---------------------------------------------------------------------------
// KDA scan. Grid (2, HH): each CTA has 4 warps (one per SMSP) and owns
// v-cols [cb*32, cb*32+32) of head h; warp w owns 8 cols. e/k/q rows are
// shared by the 4 warps through L1.
//
// Short-critical-path step:  o = (q · S_decayed) + (q · k) * delta.
// All three dot products (k·S, q·S, q·k) reduce together (interleaved
// shuffles), so only ONE 2-shfl latency round is on the serial chain.
// beta sigmoid computed INSIDE the step (prefetch stages stay pure loads —
// computing on loaded values in the load stage measurably serializes).
// ---------------------------------------------------------------------------
__device__ __forceinline__ float kda_step(float S[16],
                                          const float eg[16], const float kk[16],
                                          const float qq[16], float vv, float braw)
{
    float vp0 = 0.f, vp1 = 0.f, vp2 = 0.f, vp3 = 0.f;
    float qs0 = 0.f, qs1 = 0.f, qs2 = 0.f, qs3 = 0.f;
    float qk0 = 0.f, qk1 = 0.f, qk2 = 0.f, qk3 = 0.f;
#pragma unroll
    for (int j = 0; j < 16; j += 4) {
        float s0 = S[j + 0] * eg[j + 0]; S[j + 0] = s0;
        float s1 = S[j + 1] * eg[j + 1]; S[j + 1] = s1;
        float s2 = S[j + 2] * eg[j + 2]; S[j + 2] = s2;
        float s3 = S[j + 3] * eg[j + 3]; S[j + 3] = s3;
        vp0 = fmaf(kk[j + 0], s0, vp0); vp1 = fmaf(kk[j + 1], s1, vp1);
        vp2 = fmaf(kk[j + 2], s2, vp2); vp3 = fmaf(kk[j + 3], s3, vp3);
        qs0 = fmaf(qq[j + 0], s0, qs0); qs1 = fmaf(qq[j + 1], s1, qs1);
        qs2 = fmaf(qq[j + 2], s2, qs2); qs3 = fmaf(qq[j + 3], s3, qs3);
        qk0 = fmaf(qq[j + 0], kk[j + 0], qk0); qk1 = fmaf(qq[j + 1], kk[j + 1], qk1);
        qk2 = fmaf(qq[j + 2], kk[j + 2], qk2); qk3 = fmaf(qq[j + 3], kk[j + 3], qk3);
    }
    float vpred = (vp0 + vp1) + (vp2 + vp3);
    float qs    = (qs0 + qs1) + (qs2 + qs3);
    float qk    = (qk0 + qk1) + (qk2 + qk3);
    vpred += __shfl_xor_sync(0xffffffffu, vpred, 8);
    qs    += __shfl_xor_sync(0xffffffffu, qs, 8);
    qk    += __shfl_xor_sync(0xffffffffu, qk, 8);
    vpred += __shfl_xor_sync(0xffffffffu, vpred, 16);
    qs    += __shfl_xor_sync(0xffffffffu, qs, 16);
    qk    += __shfl_xor_sync(0xffffffffu, qk, 16);
    float b = 1.f / (1.f + __expf(-braw));     // overlaps the reductions
    float delta = (vv - vpred) * b;
#pragma unroll
    for (int j = 0; j < 16; j += 4) {
        S[j + 0] = fmaf(kk[j + 0], delta, S[j + 0]);
        S[j + 1] = fmaf(kk[j + 1], delta, S[j + 1]);
        S[j + 2] = fmaf(kk[j + 2], delta, S[j + 2]);
        S[j + 3] = fmaf(kk[j + 3], delta, S[j + 3]);
    }
    return fmaf(qk, delta, qs);
}

// egg has row stride NGE (view into combined buffer); q/k/v stride PP
__global__ void __launch_bounds__(128, 1)
kda_scan_kernel(const float* __restrict__ qg, const float* __restrict__ kg,
                const float* __restrict__ vg, const float* __restrict__ egg,
                const float* __restrict__ bg, float* __restrict__ og)
{
    const int cb      = blockIdx.x;              // col-half 0..1
    const int h       = blockIdx.y;
    const int warp    = threadIdx.x >> 5;        // 0..3 -> one per SMSP
    const int lane    = threadIdx.x & 31;
    const int quarter = lane >> 3;
    const int col     = (cb << 5) + (warp << 3) + (lane & 7);
    const int kb      = quarter << 4;

    const float* ep  = egg + h * DD + kb;
    const float* kp  = kg  + h * DD + kb;
    const float* qp  = qg  + h * DD + kb;
    const float* vpt = vg  + h * DD + col;
    const float* bpt = bg  + h;

    float S[16];
#pragma unroll
    for (int j = 0; j < 16; j++) S[j] = 0.f;

    // L2 prefetch pointers (warp 0, lanes 0..8): e/k/q/v head rows + beta
    const float* pf = nullptr;
    size_t pfstride = 0;
    if (warp == 0 && lane < 9) {
        if (lane < 8) {
            const float* bases[4] = {egg, kg, qg, vg};
            const size_t strides[4] = {NGE, PP, PP, PP};
            pf = bases[lane >> 1] + h * DD + (lane & 1) * 32;
            pfstride = strides[lane >> 1];
        } else {
            pf = bg + h;
            pfstride = HH;
        }
    }

    float ea[16], ka[16], qa[16], va, ba;
    float eb[16], kbf[16], qb[16], vb, bb;

#define LOADSTAGE(E, KA, QA, V, B, t)                                            \
    do {                                                                         \
        size_t offe = (size_t)(t) * NGE;                                         \
        size_t off  = (size_t)(t) * PP;                                          \
        _Pragma("unroll")                                                        \
        for (int j = 0; j < 16; j += 4) {                                        \
            *reinterpret_cast<float4*>(&E[j])  =                                 \
                *reinterpret_cast<const float4*>(ep + offe + j);                 \
            *reinterpret_cast<float4*>(&KA[j]) =                                 \
                *reinterpret_cast<const float4*>(kp + off + j);                  \
            *reinterpret_cast<float4*>(&QA[j]) =                                 \
                *reinterpret_cast<const float4*>(qp + off + j);                  \
        }                                                                        \
        V = vpt[off];                                                            \
        B = bpt[(size_t)(t) * HH];                                               \
    } while (0)

    LOADSTAGE(ea, ka, qa, va, ba, 0);
    LOADSTAGE(eb, kbf, qb, vb, bb, 1);

    for (int t = 0; t < TT; t += 2) {
        if (pf) {
            int tp = t + 8;
            if (tp + 1 < TT) {
                const float* p0 = pf + (size_t)tp * pfstride;
                const float* p1 = pf + (size_t)(tp + 1) * pfstride;
                asm volatile("prefetch.global.L2 [%0];" :: "l"(p0));
                asm volatile("prefetch.global.L2 [%0];" :: "l"(p1));
            }
        }
        float ov = kda_step(S, ea, ka, qa, va, ba);
        if (quarter == 0) og[(size_t)t * PP + h * DD + col] = ov;
        if (t + 2 < TT) LOADSTAGE(ea, ka, qa, va, ba, t + 2);

        ov = kda_step(S, eb, kbf, qb, vb, bb);
        if (quarter == 0) og[(size_t)(t + 1) * PP + h * DD + col] = ov;
        if (t + 3 < TT) LOADSTAGE(eb, kbf, qb, vb, bb, t + 3);
    }
#undef LOADSTAGE
}

// gated RMSNorm -> fp16 ([T, PP]); g2 strided (ld = NGE)
__global__ void rms_gate_h_kernel(const float* __restrict__ o,
                                  const float* __restrict__ g2, int ldg,
                                  const float* __restrict__ wn,
                                  __half* __restrict__ os)
{
    const int t    = blockIdx.x;
    const int h    = blockIdx.y * 8 + (threadIdx.x >> 5);
    const int lane = threadIdx.x & 31;
    size_t base  = (size_t)t * PP + h * DD;
    size_t gbase = (size_t)t * ldg + h * DD;

    float a = o[base + lane];
    float b = o[base + lane + 32];
    float ss = a * a + b * b;
    ss += __shfl_xor_sync(0xffffffffu, ss, 16);
    ss += __shfl_xor_sync(0xffffffffu, ss, 8);
    ss += __shfl_xor_sync(0xffffffffu, ss, 4);
    ss += __shfl_xor_sync(0xffffffffu, ss, 2);
    ss += __shfl_xor_sync(0xffffffffu, ss, 1);
    float r = rsqrtf(ss * (1.f / 64.f) + 1e-5f);

    float ga = g2[gbase + lane];
    float gb = g2[gbase + lane + 32];
    float va = a * r * wn[lane]      * (1.f / (1.f + __expf(-ga)));
    float vb = b * r * wn[lane + 32] * (1.f / (1.f + __expf(-gb)));

    os[base + lane]      = __float2half(va);
    os[base + lane + 32] = __float2half(vb);
}

// ---------------------------------------------------------------------------
// Host launcher
// ---------------------------------------------------------------------------
extern "C" void kernel_launch(void* const* d_in, const int* in_sizes, int n_in,
                              void* d_out, int out_size)
{
    const float* x    = (const float*)d_in[0];
    const float* Wq   = (const float*)d_in[1];
    const float* Wk   = (const float*)d_in[2];
    const float* Wv   = (const float*)d_in[3];
    const float* Wb   = (const float*)d_in[4];
    const float* Wfa  = (const float*)d_in[5];
    const float* Wfb  = (const float*)d_in[6];
    const float* dtb  = (const float*)d_in[7];
    const float* Alog = (const float*)d_in[8];
    const float* Wga  = (const float*)d_in[9];
    const float* Wgb  = (const float*)d_in[10];
    const float* cq   = (const float*)d_in[11];
    const float* ck   = (const float*)d_in[12];
    const float* cv   = (const float*)d_in[13];
    const float* wno  = (const float*)d_in[14];
    const float* Wo   = (const float*)d_in[15];
    float* out = (float*)d_out;

    static float *pxc = nullptr, *pge, *pq, *pk, *pv, *pbl;
    static __half *pxs, *pwcs, *pwos, *pos, *pags, *pwges;
    if (!pxc) {
        cudaGetSymbolAddress((void**)&pxc, d_xc);
        cudaGetSymbolAddress((void**)&pge, d_ge);
        cudaGetSymbolAddress((void**)&pq,  d_q);
        cudaGetSymbolAddress((void**)&pk,  d_k);
        cudaGetSymbolAddress((void**)&pv,  d_v);
        cudaGetSymbolAddress((void**)&pbl, d_bl);
        cudaGetSymbolAddress((void**)&pxs,  d_xs);
        cudaGetSymbolAddress((void**)&pwcs, d_wcs);
        cudaGetSymbolAddress((void**)&pwos, d_wos);
        cudaGetSymbolAddress((void**)&pos,  d_os);
        cudaGetSymbolAddress((void**)&pags, d_ags);
        cudaGetSymbolAddress((void**)&pwges, d_wges);
        cudaFuncSetAttribute(mma_gemm_kernel<false>,
                             cudaFuncAttributeMaxDynamicSharedMemorySize,
                             NSTAGE * STG_H * 2);
        cudaFuncSetAttribute(mma_gemm_kernel<true>,
                             cudaFuncAttributeMaxDynamicSharedMemorySize,
                             NSTAGE * STG_H * 2);
    }

    dim3 blk(256);
    const size_t smemMMA = NSTAGE * STG_H * 2;   // 110592 B

    // 0-4: prep needed by the projection GEMM
    convert_fp16_kernel<<<2048, 256>>>(x, pxs, (size_t)TT * HIDD);
    transpose_h_kernel<<<dim3(PP / 32, HIDD / 32), dim3(32, 8)>>>(
        Wq, pwcs + (size_t)0 * HIDD, HIDD, PP);
    transpose_h_kernel<<<dim3(PP / 32, HIDD / 32), dim3(32, 8)>>>(
        Wk, pwcs + (size_t)2048 * HIDD, HIDD, PP);
    transpose_h_kernel<<<dim3(PP / 32, HIDD / 32), dim3(32, 8)>>>(
        Wv, pwcs + (size_t)4096 * HIDD, HIDD, PP);
    pack_small_kernel<<<1024, 256>>>(Wfa, Wga, Wb, pwcs + (size_t)6144 * HIDD);

    // 5: ONE combined projection GEMM: [T, 4096] @ [4096, 6400]
    mma_gemm_kernel<false><<<dim3(NCMB / 128, TT / 128), blk, smemMMA>>>(
        pxs, pwcs, pxc, HIDD, NCMB, nullptr, nullptr);

    // 6-8: expansion path
    extract_small_kernel<<<1024, 256>>>(pxc, pags, pbl);
    pack_ge_kernel<<<512, 256>>>(Wfb, Wgb, pwges);
    mma_gemm_kernel<true><<<dim3(NGE / 128, TT / 128), blk, smemMMA>>>(
        pags, pwges, pge, KGE, NGE, dtb, Alog);

    // 9: Wo transpose (only needed by the final GEMM)
    transpose_h_kernel<<<dim3(HIDD / 32, PP / 32), dim3(32, 8)>>>(
        Wo, pwos, PP, HIDD);

    // 10-14: elementwise / scan
    dim3 cgrid(TT, HH / 8);
    conv_silu_kernel<<<cgrid, blk>>>(pxc + 0,    NCMB, cq, pq, 2);
    conv_silu_kernel<<<cgrid, blk>>>(pxc + 2048, NCMB, ck, pk, 1);
    conv_silu_kernel<<<cgrid, blk>>>(pxc + 4096, NCMB, cv, pv, 0);
    kda_scan_kernel<<<dim3(2, HH), 128>>>(pq, pk, pv, pge, pbl, pq /* o in place */);
    rms_gate_h_kernel<<<cgrid, blk>>>(pq, pge + 2048, NGE, wno, pos);

    // 15: output projection on tensor cores
    mma_gemm_kernel<false><<<dim3(HIDD / 128, TT / 128), blk, smemMMA>>>(
        pos, pwos, out, PP, HIDD, nullptr, nullptr);

    (void)in_sizes; (void)n_in; (void)out_size;
}